// round 2
// baseline (speedup 1.0000x reference)
#include <cuda_runtime.h>
#include <math.h>

#define H   512
#define S   65
#define SS  (S*S)       // 4225
#define HS  (H*S)       // 33280
#define C3H 1536
#define NCH 16          // logits h-chunks (512/32)
#define NCC 8           // linear c-chunks (1536/192)

// ------------------------- scratch (device globals) -------------------------
__device__ float g_y[HS];            // current y [H][S]
__device__ float g_K[3][HS];         // K per head slot, [H][S]
__device__ float g_Q[3][HS];
__device__ float g_V[3][HS];
__device__ float g_kqvp[4][3][HS];   // k-split partials for layers 2/3
__device__ float g_Lp[NCH][3][SS];   // logits partials
__device__ float g_SM[3][SS];        // softmax rows
__device__ float g_C[S*C3H];         // concat buffer [S][1536] (persistent across layers)
__device__ float g_linp[NCC][HS];    // linear partials
__device__ float g_zp[8][1024];      // fc1 partials
__device__ float g_z[1024];
__device__ float g_t[512];

// ------------------------- prep: y = embedding * x -------------------------
__global__ void k_prep(const float* __restrict__ inp, const float* __restrict__ emb) {
    int i = blockIdx.x * 256 + threadIdx.x;
    if (i < HS) {
        int s = i % S;
        float x = (s < 64) ? inp[s] : 1.0f;
        g_y[i] = emb[i] * x;
    }
}

// ------------------------- KQV: out[m,s] = sum_k W[m,k] * y[k,s] -----------
// grid: (nmats, 16 m-tiles of 32, KS k-splits). block 256.
// full=1 (layer 1): nmats=9, head=mat/3, type=mat%3, slot=head, KS=1 (direct write)
// full=0 (layers 2/3): nmats=3, type=mat, weight head=2, slot=0, KS=4 (partials)
__global__ void k_kqv(const float* __restrict__ wk, const float* __restrict__ wq,
                      const float* __restrict__ wv, int full) {
    __shared__ __align__(16) float Wt[32 * 33];
    __shared__ __align__(16) float Ys[2080];   // 32 k-rows x 65 s; reused for output transpose
    int mat = blockIdx.x;
    int type, whead, slot;
    if (full) { type = mat % 3; whead = mat / 3; slot = whead; }
    else      { type = mat;     whead = 2;       slot = 0;     }
    const float* Wbase = (type == 0) ? wk : ((type == 1) ? wq : wv);
    const float* W = Wbase + whead * H * H;
    int KS = gridDim.z;
    float* outp;
    if (KS == 1)
        outp = (type == 0) ? g_K[slot] : ((type == 1) ? g_Q[slot] : g_V[slot]);
    else
        outp = g_kqvp[blockIdx.z][mat];

    int m0 = blockIdx.y * 32;
    int kspan = 512 / KS;
    int k_begin = blockIdx.z * kspan;
    int k_end = k_begin + kspan;

    int tid = threadIdx.x;
    int lane = tid & 31;       // m within tile
    int w = tid >> 5;          // warp id -> s = w + 8*i
    float acc[9];
#pragma unroll
    for (int i = 0; i < 9; i++) acc[i] = 0.f;

    for (int kc = k_begin; kc < k_end; kc += 32) {
        // W tile [32m][32k] -> Wt[k][m] (pad 33 to kill write conflicts)
        for (int idx = tid; idx < 1024; idx += 256) {
            int r = idx >> 5, c = idx & 31;
            Wt[c * 33 + r] = W[(m0 + r) * H + kc + c];
        }
        // y tile: rows kc..kc+31, contiguous 2080 floats
        for (int idx = tid; idx < 2080; idx += 256)
            Ys[idx] = g_y[kc * 65 + idx];
        __syncthreads();
#pragma unroll 4
        for (int k = 0; k < 32; k++) {
            float wval = Wt[k * 33 + lane];
#pragma unroll
            for (int i = 0; i < 8; i++)
                acc[i] += wval * Ys[k * 65 + w + 8 * i];
            if (w == 0) acc[8] += wval * Ys[k * 65 + 64];
        }
        __syncthreads();
    }
    // transpose through smem for coalesced global write (reuse Ys)
#pragma unroll
    for (int i = 0; i < 8; i++) Ys[lane * 65 + w + 8 * i] = acc[i];
    if (w == 0) Ys[lane * 65 + 64] = acc[8];
    __syncthreads();
    for (int idx = tid; idx < 2080; idx += 256)
        outp[m0 * 65 + idx] = Ys[idx];
}

// reduce 4 k-split partials into K/Q/V slot 0 (layers 2/3)
__global__ void k_kqv_reduce() {
    int mat = blockIdx.x;                 // 0=K,1=Q,2=V
    int i = blockIdx.y * 256 + threadIdx.x;
    if (i < HS) {
        float v = g_kqvp[0][mat][i] + g_kqvp[1][mat][i]
                + g_kqvp[2][mat][i] + g_kqvp[3][mat][i];
        float* outp = (mat == 0) ? g_K[0] : ((mat == 1) ? g_Q[0] : g_V[0]);
        outp[i] = v;
    }
}

// ------------------------- logits: Lp[a,b] += K[h,a]*Q[h,b] over h-chunk ---
// grid (nh, NCH). block 256.
__global__ void k_logits() {
    __shared__ __align__(16) float Ks[2080];
    __shared__ __align__(16) float Qs[2080];
    int slot = blockIdx.x;
    int hc = blockIdx.y;
    int h0 = hc * 32;
    int tid = threadIdx.x, lane = tid & 31, w = tid >> 5;
    for (int idx = tid; idx < 2080; idx += 256) {
        Ks[idx] = g_K[slot][h0 * 65 + idx];
        Qs[idx] = g_Q[slot][h0 * 65 + idx];
    }
    __syncthreads();
    float a0[9], a1[9], a2[9];
#pragma unroll
    for (int i = 0; i < 9; i++) { a0[i] = 0.f; a1[i] = 0.f; a2[i] = 0.f; }
#pragma unroll 4
    for (int k = 0; k < 32; k++) {
        float k0 = Ks[k * 65 + lane];
        float k1 = Ks[k * 65 + 32 + lane];
        float k2 = Ks[k * 65 + 64];
#pragma unroll
        for (int i = 0; i < 8; i++) {
            float qb = Qs[k * 65 + w + 8 * i];
            a0[i] += k0 * qb;
            a1[i] += k1 * qb;
            a2[i] += k2 * qb;
        }
        if (w == 0) {
            float qb = Qs[k * 65 + 64];
            a0[8] += k0 * qb;
            a1[8] += k1 * qb;
            a2[8] += k2 * qb;
        }
    }
    float* Lp = g_Lp[hc][slot];
    int ns = (w == 0) ? 9 : 8;
    for (int i = 0; i < ns; i++) {
        int b = w + 8 * i;
        Lp[lane * 65 + b] = a0[i];
        Lp[(lane + 32) * 65 + b] = a1[i];
        if (lane == 0) Lp[64 * 65 + b] = a2[i];
    }
}

// ------------------------- softmax over b (rows of L) ----------------------
// grid (nh*65), block 128
__global__ void k_softmax() {
    __shared__ float sv[128];
    int slot = blockIdx.x / 65;
    int a = blockIdx.x % 65;
    int b = threadIdx.x;
    float v = -3.0e38f;
    if (b < 65) {
        float s = 0.f;
#pragma unroll
        for (int c = 0; c < NCH; c++) s += g_Lp[c][slot][a * 65 + b];
        v = s;
    }
    sv[b] = v;
    __syncthreads();
    for (int off = 64; off > 0; off >>= 1) {
        if (b < off) sv[b] = fmaxf(sv[b], sv[b + off]);
        __syncthreads();
    }
    float mx = sv[0];
    __syncthreads();
    float e = (b < 65) ? expf(v - mx) : 0.f;
    sv[b] = e;
    __syncthreads();
    for (int off = 64; off > 0; off >>= 1) {
        if (b < off) sv[b] += sv[b + off];
        __syncthreads();
    }
    float sum = sv[0];
    if (b < 65) g_SM[slot][a * 65 + b] = e / sum;
}

// ------------------------- att: C[a, col0+h] = sum_b SM[a,b]*V[h,b] --------
// grid (nh, 16 h-chunks of 32). block 256.
__global__ void k_att() {
    __shared__ __align__(16) float SMs[4225];
    __shared__ __align__(16) float Vs[2080];
    int slot = blockIdx.x;
    int h0 = blockIdx.y * 32;
    int col0 = (gridDim.x == 3) ? slot * 512 : 1024;
    int tid = threadIdx.x, lane = tid & 31, w = tid >> 5;
    for (int idx = tid; idx < 4225; idx += 256) SMs[idx] = g_SM[slot][idx];
    for (int idx = tid; idx < 2080; idx += 256) Vs[idx] = g_V[slot][h0 * 65 + idx];
    __syncthreads();
    float acc[9];
#pragma unroll
    for (int i = 0; i < 9; i++) acc[i] = 0.f;
    for (int b = 0; b < 65; b++) {
        float vv = Vs[lane * 65 + b];
#pragma unroll
        for (int i = 0; i < 8; i++)
            acc[i] += SMs[(w + 8 * i) * 65 + b] * vv;
        if (w == 0) acc[8] += SMs[64 * 65 + b] * vv;
    }
    int ns = (w == 0) ? 9 : 8;
    for (int i = 0; i < ns; i++) {
        int a = w + 8 * i;
        g_C[a * C3H + col0 + h0 + lane] = acc[i];
    }
}

// ------------------------- linear: ypart[h,s] = sum_c C[s,c]*W[c,h] --------
// grid (16 h-chunks of 32, NCC c-chunks of 192). block 256. W: [1536][512]
__global__ void k_linear(const float* __restrict__ W) {
    __shared__ __align__(16) float Ws[1024];   // [32c][32h]
    __shared__ __align__(16) float Cs[2080];   // [65s][32c]; reused for output transpose
    int h0 = blockIdx.x * 32;
    int cc = blockIdx.y;
    int c_begin = cc * 192;
    int tid = threadIdx.x, lane = tid & 31, w = tid >> 5;
    float acc[9];
#pragma unroll
    for (int i = 0; i < 9; i++) acc[i] = 0.f;
    for (int c0 = c_begin; c0 < c_begin + 192; c0 += 32) {
        for (int idx = tid; idx < 1024; idx += 256) {
            int r = idx >> 5, hh = idx & 31;
            Ws[r * 32 + hh] = W[(c0 + r) * 512 + h0 + hh];
        }
        for (int idx = tid; idx < 2080; idx += 256) {
            int s = idx >> 5, c = idx & 31;
            Cs[idx] = g_C[s * C3H + c0 + c];
        }
        __syncthreads();
#pragma unroll 4
        for (int c = 0; c < 32; c++) {
            float wv = Ws[c * 32 + lane];
#pragma unroll
            for (int i = 0; i < 8; i++)
                acc[i] += Cs[(w + 8 * i) * 32 + c] * wv;
            if (w == 0) acc[8] += Cs[64 * 32 + c] * wv;
        }
        __syncthreads();
    }
#pragma unroll
    for (int i = 0; i < 8; i++) Cs[lane * 65 + w + 8 * i] = acc[i];
    if (w == 0) Cs[lane * 65 + 64] = acc[8];
    __syncthreads();
    for (int idx = tid; idx < 2080; idx += 256)
        g_linp[cc][h0 * 65 + idx] = Cs[idx];
}

// reduce partials + relu -> g_y
__global__ void k_reduce_relu() {
    int i = blockIdx.x * 256 + threadIdx.x;
    if (i < HS) {
        float v = 0.f;
#pragma unroll
        for (int cc = 0; cc < NCC; cc++) v += g_linp[cc][i];
        g_y[i] = fmaxf(v, 0.f);
    }
}

// ------------------------- final chain -------------------------------------
// fc1: zpart[cc][j] = sum_{c in chunk} Crow[c]*L3[c,j]; grid 64, block 256
__global__ void k_fc1(const float* __restrict__ W3) {   // [1536][1024]
    __shared__ __align__(16) float Crs[192];
    __shared__ __align__(16) float Rs[8 * 128];
    int j0 = (blockIdx.x & 7) * 128;
    int cchunk = blockIdx.x >> 3;
    int c0 = cchunk * 192;
    int tid = threadIdx.x, lane = tid & 31, w = tid >> 5;
    for (int idx = tid; idx < 192; idx += 256) Crs[idx] = g_C[64 * C3H + c0 + idx];
    __syncthreads();
    int j = j0 + lane * 4;
    float4 acc = make_float4(0.f, 0.f, 0.f, 0.f);
    for (int c = w * 24; c < w * 24 + 24; c++) {
        float cr = Crs[c];
        float4 wr = *reinterpret_cast<const float4*>(&W3[(c0 + c) * 1024 + j]);
        acc.x += cr * wr.x; acc.y += cr * wr.y;
        acc.z += cr * wr.z; acc.w += cr * wr.w;
    }
    reinterpret_cast<float4*>(Rs)[w * 32 + lane] = acc;
    __syncthreads();
    if (tid < 128) {
        float s = 0.f;
#pragma unroll
        for (int ww = 0; ww < 8; ww++) s += Rs[ww * 128 + tid];
        g_zp[cchunk][j0 + tid] = s;
    }
}

__global__ void k_fz() {
    for (int j = threadIdx.x; j < 1024; j += 256) {
        float v = 0.f;
#pragma unroll
        for (int c = 0; c < 8; c++) v += g_zp[c][j];
        g_z[j] = fmaxf(v, 0.f);
    }
}

// t[h] = tanh(sum_k z[k]*L4[k,h]); grid 8 (h-chunks of 64), block 256
__global__ void k_ft(const float* __restrict__ W4) {   // [1024][512]
    __shared__ __align__(16) float zs[1024];
    __shared__ __align__(16) float Rs[8 * 64];
    int h0 = blockIdx.x * 64;
    int tid = threadIdx.x, lane = tid & 31, w = tid >> 5;
    for (int idx = tid; idx < 1024; idx += 256) zs[idx] = g_z[idx];
    __syncthreads();
    int h = h0 + lane * 2;
    float2 acc = make_float2(0.f, 0.f);
    for (int k = w * 128; k < w * 128 + 128; k++) {
        float zv = zs[k];
        float2 wr = *reinterpret_cast<const float2*>(&W4[k * 512 + h]);
        acc.x += zv * wr.x; acc.y += zv * wr.y;
    }
    reinterpret_cast<float2*>(Rs)[w * 32 + lane] = acc;
    __syncthreads();
    if (tid < 64) {
        float s = 0.f;
#pragma unroll
        for (int ww = 0; ww < 8; ww++) s += Rs[ww * 64 + tid];
        g_t[h0 + tid] = tanhf(s);
    }
}

// out[o] = sum_k t[k]*L5[k,o]; 1 block 256
__global__ void k_fout(const float* __restrict__ W5, float* __restrict__ out) { // [512][64]
    __shared__ __align__(16) float ts[512];
    __shared__ __align__(16) float Rs[8 * 64];
    int tid = threadIdx.x, lane = tid & 31, w = tid >> 5;
    for (int idx = tid; idx < 512; idx += 256) ts[idx] = g_t[idx];
    __syncthreads();
    float acc0 = 0.f, acc1 = 0.f;
    for (int k = w * 64; k < w * 64 + 64; k++) {
        float tv = ts[k];
        acc0 += tv * W5[k * 64 + lane];
        acc1 += tv * W5[k * 64 + 32 + lane];
    }
    Rs[w * 64 + lane] = acc0;
    Rs[w * 64 + 32 + lane] = acc1;
    __syncthreads();
    if (tid < 64) {
        float s = 0.f;
#pragma unroll
        for (int ww = 0; ww < 8; ww++) s += Rs[ww * 64 + tid];
        out[tid] = s;
    }
}

// ------------------------- launcher ----------------------------------------
extern "C" void kernel_launch(void* const* d_in, const int* in_sizes, int n_in,
                              void* d_out, int out_size) {
    // Resolve inputs by element count (robust to metadata ordering).
    // Unique sizes: inputs=64, embedding=33280, linear3=1572864, linear4=524288,
    // linear5=32768. Ambiguous: wq/wk/wv (2359296 x3), linear1/linear2 (786432 x2).
    const float *inp = 0, *emb = 0, *l3 = 0, *l4 = 0, *l5 = 0;
    const float *tri[3] = {0, 0, 0};  int ntri = 0;
    const float *pr[2]  = {0, 0};     int npr  = 0;
    for (int i = 0; i < n_in; i++) {
        const float* p = (const float*)d_in[i];
        switch (in_sizes[i]) {
            case 64:      inp = p; break;
            case 33280:   emb = p; break;
            case 2359296: if (ntri < 3) tri[ntri++] = p; break;
            case 786432:  if (npr  < 2) pr[npr++]   = p; break;
            case 1572864: l3 = p; break;
            case 524288:  l4 = p; break;
            case 32768:   l5 = p; break;
            default: break;
        }
    }
    // Triple order depends on global ordering: dict order (inputs first) gives
    // wq,wk,wv; alphabetical order (embedding first) gives wk,wq,wv.
    const float *wq, *wk, *wv;
    if (n_in > 0 && in_sizes[0] == 33280) { wk = tri[0]; wq = tri[1]; wv = tri[2]; }
    else                                  { wq = tri[0]; wk = tri[1]; wv = tri[2]; }
    const float *l1 = pr[0], *l2 = pr[1];
    float* out = (float*)d_out;
    const int HH = H * H;

    k_prep<<<131, 256>>>(inp, emb);

    // ---- layer 1 (all 3 heads live) ----
    k_kqv<<<dim3(9, 16, 1), 256>>>(wk, wq, wv, 1);
    k_logits<<<dim3(3, NCH), 256>>>();
    k_softmax<<<3 * 65, 128>>>();
    k_att<<<dim3(3, 16), 256>>>();
    k_linear<<<dim3(16, NCC), 256>>>(l1);
    k_reduce_relu<<<131, 256>>>();

    // ---- layer 2 (only head 2 is consumed downstream) ----
    k_kqv<<<dim3(3, 16, 4), 256>>>(wk + 3 * HH, wq + 3 * HH, wv + 3 * HH, 0);
    k_kqv_reduce<<<dim3(3, 131), 256>>>();
    k_logits<<<dim3(1, NCH), 256>>>();
    k_softmax<<<65, 128>>>();
    k_att<<<dim3(1, 16), 256>>>();
    k_linear<<<dim3(16, NCC), 256>>>(l2);
    k_reduce_relu<<<131, 256>>>();

    // ---- layer 3 (only head 2; only row 64 of linear3 matters) ----
    k_kqv<<<dim3(3, 16, 4), 256>>>(wk + 6 * HH, wq + 6 * HH, wv + 6 * HH, 0);
    k_kqv_reduce<<<dim3(3, 131), 256>>>();
    k_logits<<<dim3(1, NCH), 256>>>();
    k_softmax<<<65, 128>>>();
    k_att<<<dim3(1, 16), 256>>>();

    // ---- final chain ----
    k_fc1<<<64, 256>>>(l3);
    k_fz<<<1, 256>>>();
    k_ft<<<8, 256>>>(l4);
    k_fout<<<1, 256>>>(l5, out);
}

// round 3
// speedup vs baseline: 1.2201x; 1.2201x over previous
#include <cuda_runtime.h>
#include <math.h>

#define H   512
#define S   65
#define SS  (S*S)       // 4225
#define HS  (H*S)       // 33280
#define C3H 1536
#define NB  148
#define NT  256

// ------------------------- scratch (device globals) -------------------------
__device__ float g_y[HS];             // current y [H][S]
__device__ float g_P[8][9][HS];       // kqv partials [kz][mat][m*65+s]
__device__ float g_Lp[16][3][SS];     // logits partials [hc][slot]
__device__ float g_C[S*C3H];          // concat buffer [S][1536]
__device__ float g_lp[32][HS];        // linear partials [cchunk]
__device__ float g_zp[8][1024];       // fc1 partials
__device__ float g_t[512];
__device__ unsigned long long g_bar[20];   // monotonic barrier counters

// ------------------------- device-wide barrier ------------------------------
__device__ __forceinline__ void gbar(int k) {
    __threadfence();
    __syncthreads();
    if (threadIdx.x == 0) {
        unsigned long long t = atomicAdd(&g_bar[k], 1ULL);
        unsigned long long target = t - (t % (unsigned long long)NB) + (unsigned long long)NB;
        volatile unsigned long long* p = &g_bar[k];
        while (*p < target) __nanosleep(64);
    }
    __syncthreads();
    __threadfence();
}

// ------------------------- shared memory union -------------------------------
// gemm:   At[2064] Bs[1040] Tr[2080] xs[65]           = 5249
// logits: Ks[2080] Qs[2080] Sm[4225]                  = 8385
// att:    Ls[4225] Vs[2080]                           = 6305
// ft:     zs[1024] Rs[1024]
#define SMEM_F 8448

// =============================================================================
// GEMM phases: out[m,s] = sum_k A[m,k] * B[k,s], M-tile 128, k-chunks of 16
// thread: lane -> m = mbase + lane + 32*mi (mi<4); warp w -> s = w + 8*si
// =============================================================================

// kqv: A = W[m*512+k] (row-major), B = y[k*65+s] (layer1: emb*x on the fly)
__device__ void phase_kqv(float* sm, const float* __restrict__ wK,
                          const float* __restrict__ wQ, const float* __restrict__ wV,
                          int layer, const float* __restrict__ emb,
                          const float* __restrict__ inp) {
    float* At = sm;            // [16][129]
    float* Bs = sm + 2064;     // [16][65]
    float* Tr = sm + 3104;     // [2080]
    float* xs = sm + 5184;     // [65]
    const int tid = threadIdx.x, lane = tid & 31, w = tid >> 5;
    const int nmats = (layer == 1) ? 9 : 3;
    const int nkz   = (layer == 1) ? 4 : 8;
    const int kspan = 512 / nkz;
    const int items = nmats * 4 * nkz;

    for (int it = blockIdx.x; it < items; it += NB) {
        int kz = it / (nmats * 4);
        int rem = it - kz * nmats * 4;
        int mat = rem >> 2, mtile = rem & 3;
        int type = (layer == 1) ? (mat % 3) : mat;
        int head = (layer == 1) ? (mat / 3) : 2;
        const float* A = ((type == 0) ? wK : (type == 1) ? wQ : wV) + head * 512 * 512;
        int mbase = mtile * 128;
        int kb0 = kz * kspan;

        float acc[4][9];
#pragma unroll
        for (int a = 0; a < 4; a++)
#pragma unroll
            for (int b = 0; b < 9; b++) acc[a][b] = 0.f;

        if (layer == 1)
            for (int i = tid; i < 65; i += NT) xs[i] = (i < 64) ? inp[i] : 1.0f;

        for (int kc = 0; kc < kspan; kc += 16) {
            int kb = kb0 + kc;
            __syncthreads();
            for (int i = tid; i < 2048; i += NT) {
                int m = i >> 4, k = i & 15;
                At[k * 129 + m] = A[(mbase + m) * 512 + kb + k];
            }
            if (layer == 1) {
                for (int i = tid; i < 1040; i += NT)
                    Bs[i] = emb[kb * 65 + i] * xs[i % 65];
            } else {
                for (int i = tid; i < 1040; i += NT)
                    Bs[i] = __ldcg(&g_y[kb * 65 + i]);
            }
            __syncthreads();
#pragma unroll
            for (int k = 0; k < 16; k++) {
                float a0 = At[k * 129 + lane];
                float a1 = At[k * 129 + 32 + lane];
                float a2 = At[k * 129 + 64 + lane];
                float a3 = At[k * 129 + 96 + lane];
#pragma unroll
                for (int si = 0; si < 8; si++) {
                    float b = Bs[k * 65 + w + 8 * si];
                    acc[0][si] += a0 * b;
                    acc[1][si] += a1 * b;
                    acc[2][si] += a2 * b;
                    acc[3][si] += a3 * b;
                }
                if (w == 0) {
                    float b = Bs[k * 65 + 64];
                    acc[0][8] += a0 * b; acc[1][8] += a1 * b;
                    acc[2][8] += a2 * b; acc[3][8] += a3 * b;
                }
            }
        }
        float* outp = &g_P[kz][mat][0];
        for (int mi = 0; mi < 4; mi++) {
            __syncthreads();
#pragma unroll
            for (int si = 0; si < 8; si++) Tr[lane * 65 + w + 8 * si] = acc[mi][si];
            if (w == 0) Tr[lane * 65 + 64] = acc[mi][8];
            __syncthreads();
            for (int i = tid; i < 2080; i += NT)
                outp[(mbase + mi * 32) * 65 + i] = Tr[i];
        }
    }
}

// linear: A = W2[k*512+m] (transposed access), B = C[s*1536+c], k=c over 1536
__device__ void phase_linear(float* sm, const float* __restrict__ W,
                             float (*dest)[HS]) {
    float* At = sm;
    float* Bs = sm + 2064;
    float* Tr = sm + 3104;
    const int tid = threadIdx.x, lane = tid & 31, w = tid >> 5;
    const int items = 4 * 32;   // 4 mtiles x 32 cchunks(48)

    for (int it = blockIdx.x; it < items; it += NB) {
        int cc = it >> 2, mtile = it & 3;
        int mbase = mtile * 128;
        int kb0 = cc * 48;
        float acc[4][9];
#pragma unroll
        for (int a = 0; a < 4; a++)
#pragma unroll
            for (int b = 0; b < 9; b++) acc[a][b] = 0.f;

        for (int kc = 0; kc < 48; kc += 16) {
            int kb = kb0 + kc;
            __syncthreads();
            for (int i = tid; i < 2048; i += NT) {
                int k = i >> 7, m = i & 127;
                At[k * 129 + m] = W[(kb + k) * 512 + mbase + m];
            }
            for (int i = tid; i < 1040; i += NT) {
                int s = i >> 4, c = i & 15;
                Bs[c * 65 + s] = __ldcg(&g_C[s * 1536 + kb + c]);
            }
            __syncthreads();
#pragma unroll
            for (int k = 0; k < 16; k++) {
                float a0 = At[k * 129 + lane];
                float a1 = At[k * 129 + 32 + lane];
                float a2 = At[k * 129 + 64 + lane];
                float a3 = At[k * 129 + 96 + lane];
#pragma unroll
                for (int si = 0; si < 8; si++) {
                    float b = Bs[k * 65 + w + 8 * si];
                    acc[0][si] += a0 * b;
                    acc[1][si] += a1 * b;
                    acc[2][si] += a2 * b;
                    acc[3][si] += a3 * b;
                }
                if (w == 0) {
                    float b = Bs[k * 65 + 64];
                    acc[0][8] += a0 * b; acc[1][8] += a1 * b;
                    acc[2][8] += a2 * b; acc[3][8] += a3 * b;
                }
            }
        }
        float* outp = &dest[cc][0];
        for (int mi = 0; mi < 4; mi++) {
            __syncthreads();
#pragma unroll
            for (int si = 0; si < 8; si++) Tr[lane * 65 + w + 8 * si] = acc[mi][si];
            if (w == 0) Tr[lane * 65 + 64] = acc[mi][8];
            __syncthreads();
            for (int i = tid; i < 2080; i += NT)
                outp[(mbase + mi * 32) * 65 + i] = Tr[i];
        }
    }
}

// logits: Lp[hc][slot][a*65+b] = sum_{h in chunk} K[h,a] * Q[h,b]
__device__ void phase_logits(float* sm, int layer) {
    float* Ks = sm;
    float* Qs = sm + 2080;
    float* Sm = sm + 4160;   // [4225]
    const int tid = threadIdx.x, lane = tid & 31, w = tid >> 5;
    const int slots = (layer == 1) ? 3 : 1;
    const int nz    = (layer == 1) ? 4 : 8;
    const int items = slots * 16;

    for (int it = blockIdx.x; it < items; it += NB) {
        int slot = it >> 4, hc = it & 15;
        int matK = (layer == 1) ? slot * 3 + 0 : 0;
        int matQ = (layer == 1) ? slot * 3 + 1 : 1;
        int h0 = hc * 32;
        __syncthreads();
        for (int i = tid; i < 2080; i += NT) {
            float k = 0.f, q = 0.f;
            for (int z = 0; z < nz; z++) {
                k += __ldcg(&g_P[z][matK][h0 * 65 + i]);
                q += __ldcg(&g_P[z][matQ][h0 * 65 + i]);
            }
            Ks[i] = k; Qs[i] = q;
        }
        __syncthreads();
        float a0[9], a1[9], a2[9];
#pragma unroll
        for (int i = 0; i < 9; i++) { a0[i] = 0.f; a1[i] = 0.f; a2[i] = 0.f; }
#pragma unroll 4
        for (int k = 0; k < 32; k++) {
            float k0 = Ks[k * 65 + lane];
            float k1 = Ks[k * 65 + 32 + lane];
            float k2 = Ks[k * 65 + 64];
#pragma unroll
            for (int si = 0; si < 8; si++) {
                float qb = Qs[k * 65 + w + 8 * si];
                a0[si] += k0 * qb; a1[si] += k1 * qb; a2[si] += k2 * qb;
            }
            if (w == 0) {
                float qb = Qs[k * 65 + 64];
                a0[8] += k0 * qb; a1[8] += k1 * qb; a2[8] += k2 * qb;
            }
        }
#pragma unroll
        for (int si = 0; si < 8; si++) {
            int b = w + 8 * si;
            Sm[lane * 65 + b] = a0[si];
            Sm[(lane + 32) * 65 + b] = a1[si];
            if (lane == 0) Sm[64 * 65 + b] = a2[si];
        }
        if (w == 0) {
            Sm[lane * 65 + 64] = a0[8];
            Sm[(lane + 32) * 65 + 64] = a1[8];
            if (lane == 0) Sm[64 * 65 + 64] = a2[8];
        }
        __syncthreads();
        float* Lp = &g_Lp[hc][slot][0];
        for (int i = tid; i < 4225; i += NT) Lp[i] = Sm[i];
    }
}

// att (softmax fused): C[a, col0+h] = sum_b softmax(L)[a,b] * V[h,b]
__device__ void phase_att(float* sm, int layer) {
    float* Ls = sm;            // [4225]
    float* Vs = sm + 4225;     // [2080]
    const int tid = threadIdx.x, lane = tid & 31, w = tid >> 5;
    const int slots = (layer == 1) ? 3 : 1;
    const int nz    = (layer == 1) ? 4 : 8;
    const int items = slots * 16;

    for (int it = blockIdx.x; it < items; it += NB) {
        int slot = it >> 4, hc = it & 15;
        int matV = (layer == 1) ? slot * 3 + 2 : 2;
        int col0 = (layer == 1) ? slot * 512 : 1024;
        int h0 = hc * 32;
        __syncthreads();
        for (int i = tid; i < 4225; i += NT) {
            float v = 0.f;
#pragma unroll
            for (int c = 0; c < 16; c++) v += __ldcg(&g_Lp[c][slot][i]);
            Ls[i] = v;
        }
        for (int i = tid; i < 2080; i += NT) {
            float v = 0.f;
            for (int z = 0; z < nz; z++) v += __ldcg(&g_P[z][matV][h0 * 65 + i]);
            Vs[i] = v;
        }
        __syncthreads();
        // softmax over b for each row a (warp w handles rows w, w+8, ...)
        for (int a = w; a < 65; a += 8) {
            float e0 = Ls[a * 65 + lane];
            float e1 = Ls[a * 65 + 32 + lane];
            float e2 = (lane == 0) ? Ls[a * 65 + 64] : -3.0e38f;
            float mx = fmaxf(e0, fmaxf(e1, e2));
#pragma unroll
            for (int off = 16; off > 0; off >>= 1)
                mx = fmaxf(mx, __shfl_xor_sync(0xffffffffu, mx, off));
            float x0 = expf(e0 - mx);
            float x1 = expf(e1 - mx);
            float x2 = (lane == 0) ? expf(e2 - mx) : 0.f;
            float ssum = x0 + x1 + x2;
#pragma unroll
            for (int off = 16; off > 0; off >>= 1)
                ssum += __shfl_xor_sync(0xffffffffu, ssum, off);
            float inv = 1.0f / ssum;
            Ls[a * 65 + lane] = x0 * inv;
            Ls[a * 65 + 32 + lane] = x1 * inv;
            if (lane == 0) Ls[a * 65 + 64] = x2 * inv;
        }
        __syncthreads();
        float acc[9];
#pragma unroll
        for (int i = 0; i < 9; i++) acc[i] = 0.f;
        for (int b = 0; b < 65; b++) {
            float vv = Vs[lane * 65 + b];
#pragma unroll
            for (int si = 0; si < 8; si++)
                acc[si] += Ls[(w + 8 * si) * 65 + b] * vv;
            if (w == 0) acc[8] += Ls[64 * 65 + b] * vv;
        }
#pragma unroll
        for (int si = 0; si < 8; si++) {
            int a = w + 8 * si;
            g_C[a * 1536 + col0 + h0 + lane] = acc[si];
        }
        if (w == 0) g_C[64 * 1536 + col0 + h0 + lane] = acc[8];
    }
}

// reduce 32 linear partials + relu -> g_y
__device__ void phase_rr() {
    int i = blockIdx.x * NT + threadIdx.x;
    if (i < HS) {
        float v = 0.f;
#pragma unroll
        for (int c = 0; c < 32; c++) v += __ldcg(&g_lp[c][i]);
        g_y[i] = fmaxf(v, 0.f);
    }
}

// fc1: zp[cc][j] = sum_{c in chunk192} C[64,c]*l3[c*1024+j]
__device__ void phase_fc1(float* sm, const float* __restrict__ W3) {
    float* Crs = sm;           // [192]
    float* Rs  = sm + 192;     // [256]
    const int tid = threadIdx.x;
    for (int it = blockIdx.x; it < 64; it += NB) {
        int jt = it & 7, cc = it >> 3;
        int c0 = cc * 192, j0 = jt * 128;
        __syncthreads();
        for (int i = tid; i < 192; i += NT)
            Crs[i] = __ldcg(&g_C[64 * 1536 + c0 + i]);
        __syncthreads();
        int j = j0 + (tid & 127);
        int chalf = (tid >> 7) * 96;
        float acc = 0.f;
        for (int c = chalf; c < chalf + 96; c++)
            acc += Crs[c] * W3[(c0 + c) * 1024 + j];
        Rs[tid] = acc;
        __syncthreads();
        if (tid < 128) g_zp[cc][j0 + tid] = Rs[tid] + Rs[tid + 128];
    }
}

// ft: z = relu(sum zp); t[h] = tanh(sum_k z[k]*l4[k*512+h])
__device__ void phase_ft(float* sm, const float* __restrict__ W4) {
    float* zs = sm;            // [1024]
    float* Rs = sm + 1024;     // [8][128]
    const int tid = threadIdx.x, lane = tid & 31, w = tid >> 5;
    for (int it = blockIdx.x; it < 4; it += NB) {
        int h0 = it * 128;
        __syncthreads();
        for (int i = tid; i < 1024; i += NT) {
            float v = 0.f;
#pragma unroll
            for (int c = 0; c < 8; c++) v += __ldcg(&g_zp[c][i]);
            zs[i] = fmaxf(v, 0.f);
        }
        __syncthreads();
        float4 a4 = make_float4(0.f, 0.f, 0.f, 0.f);
        int hh = h0 + lane * 4;
        for (int k = w * 128; k < w * 128 + 128; k++) {
            float zv = zs[k];
            float4 wr = *reinterpret_cast<const float4*>(&W4[k * 512 + hh]);
            a4.x += zv * wr.x; a4.y += zv * wr.y;
            a4.z += zv * wr.z; a4.w += zv * wr.w;
        }
        Rs[w * 128 + lane * 4 + 0] = a4.x;
        Rs[w * 128 + lane * 4 + 1] = a4.y;
        Rs[w * 128 + lane * 4 + 2] = a4.z;
        Rs[w * 128 + lane * 4 + 3] = a4.w;
        __syncthreads();
        if (tid < 128) {
            float s = 0.f;
#pragma unroll
            for (int ww = 0; ww < 8; ww++) s += Rs[ww * 128 + tid];
            g_t[h0 + tid] = tanhf(s);
        }
    }
}

// fout: out[o] = sum_k t[k]*l5[k*64+o]   (block 0 only)
__device__ void phase_fout(float* sm, const float* __restrict__ W5,
                           float* __restrict__ out) {
    float* ts = sm;            // [512]
    float* Rs = sm + 512;      // [8][64]
    const int tid = threadIdx.x, lane = tid & 31, w = tid >> 5;
    for (int i = tid; i < 512; i += NT) ts[i] = __ldcg(&g_t[i]);
    __syncthreads();
    float acc0 = 0.f, acc1 = 0.f;
    for (int k = w * 64; k < w * 64 + 64; k++) {
        float tv = ts[k];
        acc0 += tv * W5[k * 64 + lane];
        acc1 += tv * W5[k * 64 + 32 + lane];
    }
    Rs[w * 64 + lane] = acc0;
    Rs[w * 64 + 32 + lane] = acc1;
    __syncthreads();
    if (tid < 64) {
        float s = 0.f;
#pragma unroll
        for (int ww = 0; ww < 8; ww++) s += Rs[ww * 64 + tid];
        out[tid] = s;
    }
}

// =============================================================================
__global__ __launch_bounds__(NT, 1)
void persist_kernel(const float* __restrict__ inp, const float* __restrict__ emb,
                    const float* __restrict__ wk, const float* __restrict__ wq,
                    const float* __restrict__ wv,
                    const float* __restrict__ l1, const float* __restrict__ l2,
                    const float* __restrict__ l3, const float* __restrict__ l4,
                    const float* __restrict__ l5, float* __restrict__ out) {
    __shared__ __align__(16) float sm[SMEM_F];
    const int HH = 512 * 512 * 3;   // one layer's 3-head weight block

    // ---- layer 1 ----
    phase_kqv(sm, wk, wq, wv, 1, emb, inp);          gbar(0);
    phase_logits(sm, 1);                             gbar(1);
    phase_att(sm, 1);                                gbar(2);
    phase_linear(sm, l1, g_lp);                      gbar(3);
    phase_rr();                                      gbar(4);
    // ---- layer 2 ----
    phase_kqv(sm, wk + HH, wq + HH, wv + HH, 2, emb, inp);  gbar(5);
    phase_logits(sm, 2);                             gbar(6);
    phase_att(sm, 2);                                gbar(7);
    phase_linear(sm, l2, g_lp);                      gbar(8);
    phase_rr();                                      gbar(9);
    // ---- layer 3 ----
    phase_kqv(sm, wk + 2 * HH, wq + 2 * HH, wv + 2 * HH, 3, emb, inp);  gbar(10);
    phase_logits(sm, 3);                             gbar(11);
    phase_att(sm, 3);                                gbar(12);
    // ---- final chain ----
    phase_fc1(sm, l3);                               gbar(13);
    phase_ft(sm, l4);                                gbar(14);
    if (blockIdx.x == 0) phase_fout(sm, l5, out);
}

// ------------------------- launcher ----------------------------------------
extern "C" void kernel_launch(void* const* d_in, const int* in_sizes, int n_in,
                              void* d_out, int out_size) {
    // Resolve inputs by element count (robust to metadata ordering).
    const float *inp = 0, *emb = 0, *l3 = 0, *l4 = 0, *l5 = 0;
    const float *tri[3] = {0, 0, 0};  int ntri = 0;
    const float *pr[2]  = {0, 0};     int npr  = 0;
    for (int i = 0; i < n_in; i++) {
        const float* p = (const float*)d_in[i];
        switch (in_sizes[i]) {
            case 64:      inp = p; break;
            case 33280:   emb = p; break;
            case 2359296: if (ntri < 3) tri[ntri++] = p; break;
            case 786432:  if (npr  < 2) pr[npr++]   = p; break;
            case 1572864: l3 = p; break;
            case 524288:  l4 = p; break;
            case 32768:   l5 = p; break;
            default: break;
        }
    }
    const float *wq, *wk, *wv;
    if (n_in > 0 && in_sizes[0] == 33280) { wk = tri[0]; wq = tri[1]; wv = tri[2]; }
    else                                  { wq = tri[0]; wk = tri[1]; wv = tri[2]; }
    const float *l1 = pr[0], *l2 = pr[1];
    float* out = (float*)d_out;

    persist_kernel<<<NB, NT>>>(inp, emb, wk, wq, wv, l1, l2, l3, l4, l5, out);
}

// round 4
// speedup vs baseline: 1.4163x; 1.1607x over previous
#include <cuda_runtime.h>
#include <math.h>

#define H    512
#define S    65
#define SS   (S*S)       // 4225
#define HS   (H*S)       // 33280
#define NB   148
#define NT   512
#define ULL  unsigned long long

// ------------------------- scratch (device globals) -------------------------
__device__ float g_y[HS];             // current y [H][S]
__device__ float g_P[8][9][HS];       // kqv partials [kz][mat][m*65+s]
__device__ float g_Lp[16][3][SS];     // logits partials [hc][slot]
__device__ float g_C[S*1536];         // concat buffer [S][1536]
__device__ float g_lp[16][HS];        // linear partials [cchunk]
__device__ float g_zp[8][1024];       // fc1 partials
__device__ float g_t[512];
__device__ unsigned long long g_bar[20];   // monotonic barrier counters

// ------------------------- packed f32x2 helpers -----------------------------
#define FMA2(acc, a, b) asm("fma.rn.f32x2 %0, %1, %2, %0;" : "+l"(acc) : "l"(a), "l"(b))
#define PACK2(d, x)     asm("mov.b64 %0, {%1, %1};" : "=l"(d) : "f"(x))
#define UNPK2(lo, hi, v) asm("mov.b64 {%0, %1}, %2;" : "=f"(lo), "=f"(hi) : "l"(v))

// ------------------------- device-wide barrier ------------------------------
__device__ __forceinline__ void gbar(int k) {
    __threadfence();
    __syncthreads();
    if (threadIdx.x == 0) {
        unsigned long long t = atomicAdd(&g_bar[k], 1ULL);
        unsigned long long target = t - (t % (unsigned long long)NB) + (unsigned long long)NB;
        volatile unsigned long long* p = &g_bar[k];
        while (*p < target) __nanosleep(64);
    }
    __syncthreads();
    __threadfence();
}

// shared-memory pool (floats):
// GEMM:   A0[1056] A1[1056] B0[1088] B1[1088] Tr[4160]   = 8448
// LOGITS: Ks[2112] Qs[2176] Sm[4225]                     = 8513
// ATT:    Ls[4225] Vs[2080]                              = 6305
#define SMEM_F 8576

// =============================================================================
// GEMM item: out[m,s] = sum_k A.[m,k] * B[k,s].  m-tile 64, k-chunks of 16.
// mode 0 (kqv):   A row-major W[m*512+k],           B = g_y[k*65+s]
// mode 1 (linear):A col-of-W  W[(kb+k)*512+m],      B = g_C[s*1536+kb+c]
// thread: lane -> m = {lane, lane+32}; warp w(16) -> s = 4w+si (w0 also s=64)
// =============================================================================
__device__ __forceinline__ void gemm_prefetch(const float* __restrict__ A,
        int mbase, int kb, int mode,
        float& ar0, float& ar1, float& br0, float& br1, float& br2) {
    const int tid = threadIdx.x;
    if (mode == 0) {
        ar0 = A[(mbase + (tid >> 4)) * 512 + kb + (tid & 15)];
        ar1 = A[(mbase + (tid >> 4) + 32) * 512 + kb + (tid & 15)];
        br0 = __ldcg(&g_y[kb * 65 + tid]);
        br1 = __ldcg(&g_y[kb * 65 + 512 + tid]);
        br2 = (tid < 16) ? __ldcg(&g_y[kb * 65 + 1024 + tid]) : 0.f;
    } else {
        ar0 = A[(kb + (tid >> 6)) * 512 + mbase + (tid & 63)];
        ar1 = A[(kb + (tid >> 6) + 8) * 512 + mbase + (tid & 63)];
        br0 = __ldcg(&g_C[(tid >> 4) * 1536 + kb + (tid & 15)]);
        br1 = __ldcg(&g_C[((tid >> 4) + 32) * 1536 + kb + (tid & 15)]);
        br2 = (tid < 16) ? __ldcg(&g_C[64 * 1536 + kb + tid]) : 0.f;
    }
}

__device__ __forceinline__ void gemm_store(float* At, float* Bs, int mode,
        float ar0, float ar1, float br0, float br1, float br2) {
    const int tid = threadIdx.x;
    if (mode == 0) {
        At[(tid & 15) * 66 + (tid >> 4)] = ar0;
        At[(tid & 15) * 66 + (tid >> 4) + 32] = ar1;
        int j = tid;        Bs[(j / 65) * 68 + (j % 65)] = br0;
        j = tid + 512;      Bs[(j / 65) * 68 + (j % 65)] = br1;
        if (tid < 16) { j = 1024 + tid; Bs[(j / 65) * 68 + (j % 65)] = br2; }
    } else {
        At[(tid >> 6) * 66 + (tid & 63)] = ar0;
        At[((tid >> 6) + 8) * 66 + (tid & 63)] = ar1;
        Bs[(tid & 15) * 68 + (tid >> 4)] = br0;
        Bs[(tid & 15) * 68 + (tid >> 4) + 32] = br1;
        if (tid < 16) Bs[tid * 68 + 64] = br2;
    }
}

__device__ __forceinline__ void gemm_item(float* sm, const float* __restrict__ A,
        int mbase, int kb0, int nchunks, int mode, float* __restrict__ outp) {
    const int tid = threadIdx.x, lane = tid & 31, w = tid >> 5;
    float* Ab0 = sm;          float* Ab1 = sm + 1056;
    float* Bb0 = sm + 2112;   float* Bb1 = sm + 3200;
    float* Tr  = sm + 4288;   // [64][65] = 4160

    float ar0, ar1, br0, br1, br2;
    gemm_prefetch(A, mbase, kb0, mode, ar0, ar1, br0, br1, br2);
    gemm_store(Ab0, Bb0, mode, ar0, ar1, br0, br1, br2);
    __syncthreads();

    ULL a00 = 0, a01 = 0, a10 = 0, a11 = 0;
    float t0 = 0.f, t1 = 0.f;

    for (int c = 0; c < nchunks; c++) {
        if (c + 1 < nchunks)
            gemm_prefetch(A, mbase, kb0 + (c + 1) * 16, mode, ar0, ar1, br0, br1, br2);
        float* At = (c & 1) ? Ab1 : Ab0;
        float* Bs = (c & 1) ? Bb1 : Bb0;
#pragma unroll
        for (int k = 0; k < 16; k++) {
            float x0 = At[k * 66 + lane];
            float x1 = At[k * 66 + 32 + lane];
            ULL pa0, pa1;
            PACK2(pa0, x0);
            PACK2(pa1, x1);
            ULL pb01 = *(const ULL*)(Bs + k * 68 + (w << 2));
            ULL pb23 = *(const ULL*)(Bs + k * 68 + (w << 2) + 2);
            FMA2(a00, pa0, pb01); FMA2(a01, pa0, pb23);
            FMA2(a10, pa1, pb01); FMA2(a11, pa1, pb23);
            if (w == 0) {
                float b = Bs[k * 68 + 64];
                t0 = fmaf(x0, b, t0);
                t1 = fmaf(x1, b, t1);
            }
        }
        if (c + 1 < nchunks) {
            gemm_store((c & 1) ? Ab0 : Ab1, (c & 1) ? Bb0 : Bb1, mode,
                       ar0, ar1, br0, br1, br2);
            __syncthreads();
        }
    }
    // write accumulators to Tr then coalesced copy out
    {
        float s0, s1;
        UNPK2(s0, s1, a00); Tr[lane * 65 + 4 * w] = s0;            Tr[lane * 65 + 4 * w + 1] = s1;
        UNPK2(s0, s1, a01); Tr[lane * 65 + 4 * w + 2] = s0;        Tr[lane * 65 + 4 * w + 3] = s1;
        UNPK2(s0, s1, a10); Tr[(lane + 32) * 65 + 4 * w] = s0;     Tr[(lane + 32) * 65 + 4 * w + 1] = s1;
        UNPK2(s0, s1, a11); Tr[(lane + 32) * 65 + 4 * w + 2] = s0; Tr[(lane + 32) * 65 + 4 * w + 3] = s1;
        if (w == 0) { Tr[lane * 65 + 64] = t0; Tr[(lane + 32) * 65 + 64] = t1; }
    }
    __syncthreads();
    for (int i = tid; i < 4160; i += NT)
        outp[mbase * 65 + i] = Tr[i];
}

// ------------------------- prep: y = embedding * x --------------------------
__device__ void phase_prep(const float* __restrict__ inp, const float* __restrict__ emb) {
    for (int i = blockIdx.x * NT + threadIdx.x; i < HS; i += NB * NT) {
        int s = i % 65;
        float x = (s < 64) ? __ldg(&inp[s]) : 1.0f;
        g_y[i] = emb[i] * x;
    }
}

// ------------------------- kqv phase ----------------------------------------
__device__ void phase_kqv(float* sm, const float* __restrict__ wK,
                          const float* __restrict__ wQ, const float* __restrict__ wV,
                          int layer) {
    const int nmats = (layer == 1) ? 9 : 3;
    const int nkz   = (layer == 1) ? 2 : 8;
    const int kspan = 512 / nkz;
    const int nchunks = kspan / 16;
    const int items = nmats * 8 * nkz;
    const int per = nmats * 8;
    for (int it = blockIdx.x; it < items; it += NB) {
        int kz = it / per, rem = it - kz * per;
        int mat = rem >> 3, mtile = rem & 7;
        int type = (layer == 1) ? (mat % 3) : mat;
        int head = (layer == 1) ? (mat / 3) : 2;
        const float* A = ((type == 0) ? wK : (type == 1) ? wQ : wV) + head * 512 * 512;
        gemm_item(sm, A, mtile * 64, kz * kspan, nchunks, 0, &g_P[kz][mat][0]);
    }
}

// ------------------------- linear phase -------------------------------------
__device__ void phase_linear(float* sm, const float* __restrict__ W) {
    for (int it = blockIdx.x; it < 128; it += NB) {
        int cc = it >> 3, mtile = it & 7;
        gemm_item(sm, W, mtile * 64, cc * 96, 6, 1, &g_lp[cc][0]);
    }
}

// ------------------------- logits phase -------------------------------------
__device__ void phase_logits(float* sm, int layer) {
    float* Ks = sm;           // [32][66]
    float* Qs = sm + 2112;    // [32][68]
    float* Sm = sm + 4288;    // [4225]
    const int tid = threadIdx.x, lane = tid & 31, w = tid >> 5;
    const int slots = (layer == 1) ? 3 : 1;
    const int nz    = (layer == 1) ? 2 : 8;
    const int items = slots * 16;
    for (int it = blockIdx.x; it < items; it += NB) {
        int slot = it >> 4, hc = it & 15, h0 = hc * 32;
        int matK = (layer == 1) ? slot * 3 : 0;
        int matQ = matK + 1;
        __syncthreads();
        for (int i = tid; i < 2080; i += NT) {
            int h = i / 65, a = i % 65;
            float kv = 0.f, qv = 0.f;
            for (int z = 0; z < nz; z++) {
                kv += __ldcg(&g_P[z][matK][h0 * 65 + i]);
                qv += __ldcg(&g_P[z][matQ][h0 * 65 + i]);
            }
            Ks[h * 66 + a] = kv;
            Qs[h * 68 + a] = qv;
        }
        __syncthreads();
        float r0[4] = {0,0,0,0}, r1[4] = {0,0,0,0}, r2[4] = {0,0,0,0};
        float u0 = 0.f, u1 = 0.f, u2 = 0.f;
#pragma unroll 8
        for (int h = 0; h < 32; h++) {
            float k0 = Ks[h * 66 + lane];
            float k1 = Ks[h * 66 + 32 + lane];
            float k2 = Ks[h * 66 + 64];
            float4 q = *(const float4*)(Qs + h * 68 + 4 * w);
            r0[0] = fmaf(k0, q.x, r0[0]); r0[1] = fmaf(k0, q.y, r0[1]);
            r0[2] = fmaf(k0, q.z, r0[2]); r0[3] = fmaf(k0, q.w, r0[3]);
            r1[0] = fmaf(k1, q.x, r1[0]); r1[1] = fmaf(k1, q.y, r1[1]);
            r1[2] = fmaf(k1, q.z, r1[2]); r1[3] = fmaf(k1, q.w, r1[3]);
            r2[0] = fmaf(k2, q.x, r2[0]); r2[1] = fmaf(k2, q.y, r2[1]);
            r2[2] = fmaf(k2, q.z, r2[2]); r2[3] = fmaf(k2, q.w, r2[3]);
            if (w == 0) {
                float q64 = Qs[h * 68 + 64];
                u0 = fmaf(k0, q64, u0); u1 = fmaf(k1, q64, u1); u2 = fmaf(k2, q64, u2);
            }
        }
#pragma unroll
        for (int si = 0; si < 4; si++) {
            int b = 4 * w + si;
            Sm[lane * 65 + b] = r0[si];
            Sm[(lane + 32) * 65 + b] = r1[si];
            if (lane == 0) Sm[64 * 65 + b] = r2[si];
        }
        if (w == 0) {
            Sm[lane * 65 + 64] = u0;
            Sm[(lane + 32) * 65 + 64] = u1;
            if (lane == 0) Sm[64 * 65 + 64] = u2;
        }
        __syncthreads();
        float* Lp = &g_Lp[hc][slot][0];
        for (int i = tid; i < 4225; i += NT) Lp[i] = Sm[i];
    }
}

// ------------------------- att phase (softmax fused) ------------------------
__device__ void phase_att(float* sm, int layer) {
    float* Ls = sm;            // [4225]
    float* Vs = sm + 4225;     // [32][65]
    const int tid = threadIdx.x, lane = tid & 31, w = tid >> 5;
    const int slots = (layer == 1) ? 3 : 1;
    const int nz    = (layer == 1) ? 2 : 8;
    const int items = slots * 16;
    for (int it = blockIdx.x; it < items; it += NB) {
        int slot = it >> 4, hc = it & 15, h0 = hc * 32;
        int matV = (layer == 1) ? slot * 3 + 2 : 2;
        int col0 = (layer == 1) ? slot * 512 : 1024;
        __syncthreads();
        for (int i = tid; i < 4225; i += NT) {
            float v = 0.f;
#pragma unroll
            for (int c = 0; c < 16; c++) v += __ldcg(&g_Lp[c][slot][i]);
            Ls[i] = v;
        }
        for (int i = tid; i < 2080; i += NT) {
            float v = 0.f;
            for (int z = 0; z < nz; z++) v += __ldcg(&g_P[z][matV][h0 * 65 + i]);
            Vs[i] = v;
        }
        __syncthreads();
        for (int a = w; a < 65; a += 16) {
            float e0 = Ls[a * 65 + lane];
            float e1 = Ls[a * 65 + 32 + lane];
            float e2 = (lane == 0) ? Ls[a * 65 + 64] : -3.0e38f;
            float mx = fmaxf(e0, fmaxf(e1, e2));
#pragma unroll
            for (int off = 16; off > 0; off >>= 1)
                mx = fmaxf(mx, __shfl_xor_sync(0xffffffffu, mx, off));
            float x0 = expf(e0 - mx);
            float x1 = expf(e1 - mx);
            float x2 = (lane == 0) ? expf(e2 - mx) : 0.f;
            float ssum = x0 + x1 + x2;
#pragma unroll
            for (int off = 16; off > 0; off >>= 1)
                ssum += __shfl_xor_sync(0xffffffffu, ssum, off);
            float inv = 1.0f / ssum;
            Ls[a * 65 + lane] = x0 * inv;
            Ls[a * 65 + 32 + lane] = x1 * inv;
            if (lane == 0) Ls[a * 65 + 64] = x2 * inv;
        }
        __syncthreads();
        float acc[4] = {0,0,0,0};
        float t = 0.f;
        for (int b = 0; b < 65; b++) {
            float vv = Vs[lane * 65 + b];
#pragma unroll
            for (int si = 0; si < 4; si++)
                acc[si] = fmaf(Ls[(4 * w + si) * 65 + b], vv, acc[si]);
            if (w == 0) t = fmaf(Ls[64 * 65 + b], vv, t);
        }
#pragma unroll
        for (int si = 0; si < 4; si++)
            g_C[(4 * w + si) * 1536 + col0 + h0 + lane] = acc[si];
        if (w == 0) g_C[64 * 1536 + col0 + h0 + lane] = t;
    }
}

// ------------------------- reduce + relu -> g_y ------------------------------
__device__ void phase_rr() {
    for (int i = blockIdx.x * NT + threadIdx.x; i < HS; i += NB * NT) {
        float v = 0.f;
#pragma unroll
        for (int c = 0; c < 16; c++) v += __ldcg(&g_lp[c][i]);
        g_y[i] = fmaxf(v, 0.f);
    }
}

// ------------------------- final chain --------------------------------------
__device__ void phase_fc1(float* sm, const float* __restrict__ W3) {   // [1536][1024]
    float* Crs = sm;           // [192]
    float* Rs  = sm + 192;     // [512]
    const int tid = threadIdx.x;
    for (int it = blockIdx.x; it < 64; it += NB) {
        int jt = it & 7, cc = it >> 3;
        int c0 = cc * 192, j0 = jt * 128;
        __syncthreads();
        for (int i = tid; i < 192; i += NT)
            Crs[i] = __ldcg(&g_C[64 * 1536 + c0 + i]);
        __syncthreads();
        int j = j0 + (tid & 127);
        int q = tid >> 7;   // 0..3
        float acc = 0.f;
        for (int c = q * 48; c < q * 48 + 48; c++)
            acc = fmaf(Crs[c], W3[(c0 + c) * 1024 + j], acc);
        Rs[tid] = acc;
        __syncthreads();
        if (tid < 128)
            g_zp[cc][j0 + tid] = Rs[tid] + Rs[tid + 128] + Rs[tid + 256] + Rs[tid + 384];
    }
}

__device__ void phase_ft(float* sm, const float* __restrict__ W4) {   // [1024][512]
    float* zs = sm;            // [1024]
    float* Rs = sm + 1024;     // [16][128]
    const int tid = threadIdx.x, lane = tid & 31, w = tid >> 5;
    for (int it = blockIdx.x; it < 4; it += NB) {
        int h0 = it * 128;
        __syncthreads();
        for (int i = tid; i < 1024; i += NT) {
            float v = 0.f;
#pragma unroll
            for (int c = 0; c < 8; c++) v += __ldcg(&g_zp[c][i]);
            zs[i] = fmaxf(v, 0.f);
        }
        __syncthreads();
        int hh = h0 + lane * 4;
        float4 a = make_float4(0.f, 0.f, 0.f, 0.f);
        for (int k = w * 64; k < w * 64 + 64; k++) {
            float zv = zs[k];
            float4 wr = *(const float4*)(&W4[k * 512 + hh]);
            a.x = fmaf(zv, wr.x, a.x); a.y = fmaf(zv, wr.y, a.y);
            a.z = fmaf(zv, wr.z, a.z); a.w = fmaf(zv, wr.w, a.w);
        }
        Rs[w * 128 + lane * 4 + 0] = a.x;
        Rs[w * 128 + lane * 4 + 1] = a.y;
        Rs[w * 128 + lane * 4 + 2] = a.z;
        Rs[w * 128 + lane * 4 + 3] = a.w;
        __syncthreads();
        if (tid < 128) {
            float s = 0.f;
#pragma unroll
            for (int ww = 0; ww < 16; ww++) s += Rs[ww * 128 + tid];
            g_t[h0 + tid] = tanhf(s);
        }
    }
}

__device__ void phase_fout(float* sm, const float* __restrict__ W5,
                           float* __restrict__ out) {   // [512][64]
    float* ts = sm;            // [512]
    float* Rs = sm + 512;      // [16][64]
    const int tid = threadIdx.x, lane = tid & 31, w = tid >> 5;
    for (int i = tid; i < 512; i += NT) ts[i] = __ldcg(&g_t[i]);
    __syncthreads();
    float acc0 = 0.f, acc1 = 0.f;
    for (int k = w * 32; k < w * 32 + 32; k++) {
        float tv = ts[k];
        acc0 = fmaf(tv, W5[k * 64 + lane], acc0);
        acc1 = fmaf(tv, W5[k * 64 + 32 + lane], acc1);
    }
    Rs[w * 64 + lane] = acc0;
    Rs[w * 64 + 32 + lane] = acc1;
    __syncthreads();
    if (tid < 64) {
        float s = 0.f;
#pragma unroll
        for (int ww = 0; ww < 16; ww++) s += Rs[ww * 64 + tid];
        out[tid] = s;
    }
}

// =============================================================================
__global__ __launch_bounds__(NT, 1)
void persist_kernel(const float* __restrict__ inp, const float* __restrict__ emb,
                    const float* __restrict__ wk, const float* __restrict__ wq,
                    const float* __restrict__ wv,
                    const float* __restrict__ l1, const float* __restrict__ l2,
                    const float* __restrict__ l3, const float* __restrict__ l4,
                    const float* __restrict__ l5, float* __restrict__ out) {
    __shared__ __align__(16) float sm[SMEM_F];
    const int HH = 512 * 512 * 3;   // one layer's 3-head weight block

    phase_prep(inp, emb);                            gbar(0);
    // ---- layer 1 ----
    phase_kqv(sm, wk, wq, wv, 1);                    gbar(1);
    phase_logits(sm, 1);                             gbar(2);
    phase_att(sm, 1);                                gbar(3);
    phase_linear(sm, l1);                            gbar(4);
    phase_rr();                                      gbar(5);
    // ---- layer 2 ----
    phase_kqv(sm, wk + HH, wq + HH, wv + HH, 2);     gbar(6);
    phase_logits(sm, 2);                             gbar(7);
    phase_att(sm, 2);                                gbar(8);
    phase_linear(sm, l2);                            gbar(9);
    phase_rr();                                      gbar(10);
    // ---- layer 3 ----
    phase_kqv(sm, wk + 2 * HH, wq + 2 * HH, wv + 2 * HH, 3);  gbar(11);
    phase_logits(sm, 3);                             gbar(12);
    phase_att(sm, 3);                                gbar(13);
    // ---- final chain ----
    phase_fc1(sm, l3);                               gbar(14);
    phase_ft(sm, l4);                                gbar(15);
    if (blockIdx.x == 0) phase_fout(sm, l5, out);
}

// ------------------------- launcher ----------------------------------------
extern "C" void kernel_launch(void* const* d_in, const int* in_sizes, int n_in,
                              void* d_out, int out_size) {
    // Resolve inputs by element count (robust to metadata ordering).
    const float *inp = 0, *emb = 0, *l3 = 0, *l4 = 0, *l5 = 0;
    const float *tri[3] = {0, 0, 0};  int ntri = 0;
    const float *pr[2]  = {0, 0};     int npr  = 0;
    for (int i = 0; i < n_in; i++) {
        const float* p = (const float*)d_in[i];
        switch (in_sizes[i]) {
            case 64:      inp = p; break;
            case 33280:   emb = p; break;
            case 2359296: if (ntri < 3) tri[ntri++] = p; break;
            case 786432:  if (npr  < 2) pr[npr++]   = p; break;
            case 1572864: l3 = p; break;
            case 524288:  l4 = p; break;
            case 32768:   l5 = p; break;
            default: break;
        }
    }
    const float *wq, *wk, *wv;
    if (n_in > 0 && in_sizes[0] == 33280) { wk = tri[0]; wq = tri[1]; wv = tri[2]; }
    else                                  { wq = tri[0]; wk = tri[1]; wv = tri[2]; }
    const float *l1 = pr[0], *l2 = pr[1];
    float* out = (float*)d_out;

    persist_kernel<<<NB, NT>>>(inp, emb, wk, wq, wv, l1, l2, l3, l4, l5, out);
}